// round 17
// baseline (speedup 1.0000x reference)
#include <cuda_runtime.h>
#include <cstdint>

#define M_NODES 150000      // 3 * NATOMS
#define M_HALF  75000
#define NE_EDGES 1500000
#define NE_HALF  750000
#define NHEADS 4
#define DHEAD 16

typedef unsigned long long ull;

// Device-global scratch
__device__ float g_t4[M_NODES * 4];       // per-node low-rank features
__device__ float g_UZ[M_NODES * 20];      // [4 heads x 4 U] + [4 Z]
// P tensor packed by HEAD PAIR: g_P2[k*32 + hp*16 + p] = (P^{2hp}_{p,k}, P^{2hp+1}_{p,k})
__device__ ull   g_P2[17 * 2 * 16];
// out_kernel tables (dup-packed)
__device__ ull   g_Wod[64 * 16];          // dup(Wout[d*16+k])
__device__ ull   g_ACd[64 * 6];           // per d: dup(A0..A3), dup(c), pad
__device__ int   g_idx_is_64;

__device__ __forceinline__ float elu1(float v) {
    return v > 0.0f ? v : (__expf(v) - 1.0f);
}

__device__ __forceinline__ void red_add_v4(float* addr, float4 v) {
    asm volatile("red.global.add.v4.f32 [%0], {%1, %2, %3, %4};"
                 :: "l"(addr), "f"(v.x), "f"(v.y), "f"(v.z), "f"(v.w)
                 : "memory");
}

// packed f32x2 helpers (Blackwell): FFMA2 via PTX only
__device__ __forceinline__ ull pk2(float lo, float hi) {
    ull r; asm("mov.b64 %0, {%1, %2};" : "=l"(r) : "f"(lo), "f"(hi)); return r;
}
__device__ __forceinline__ void upk2(float& lo, float& hi, ull v) {
    asm("mov.b64 {%0, %1}, %2;" : "=f"(lo), "=f"(hi) : "l"(v));
}
__device__ __forceinline__ void fma2(ull& d, ull a, ull b) {   // d = a*b + d
    asm("fma.rn.f32x2 %0, %1, %2, %0;" : "+l"(d) : "l"(a), "l"(b));
}
__device__ __forceinline__ ull mul2(ull a, ull b) {
    ull r; asm("mul.rn.f32x2 %0, %1, %2;" : "=l"(r) : "l"(a), "l"(b)); return r;
}
__device__ __forceinline__ ull add2(ull a, ull b) {
    ull r; asm("add.rn.f32x2 %0, %1, %2;" : "=l"(r) : "l"(a), "l"(b)); return r;
}
__device__ __forceinline__ ull dupf(float v) {
    uint32_t b = __float_as_uint(v);
    return (ull)b | ((ull)b << 32);
}

// (i,j) pair enumeration, i<=j, p = 0..14
__device__ __constant__ int c_PI[15] = {0,0,0,0,0,1,1,1,1,2,2,2,3,3,4};
__device__ __constant__ int c_PJ[15] = {0,1,2,3,4,1,2,3,4,2,3,4,3,4,4};

// ---------------------------------------------------------------------------
__global__ void probe_idx_kernel(const int* __restrict__ ei32) {
    int z = (ei32[1] == 0) & (ei32[3] == 0) & (ei32[5] == 0) & (ei32[7] == 0);
    g_idx_is_64 = z;
}

// ---------------------------------------------------------------------------
// Setup: A = W2@W, c = b2@W + b; P^h packed by head pair; out_kernel tables.
// ---------------------------------------------------------------------------
__global__ void setup_kernel(const float* __restrict__ W2, const float* __restrict__ b2,
                             const float* __restrict__ W,  const float* __restrict__ b,
                             const float* __restrict__ Wout) {
    __shared__ float shA[5 * 64];       // At[i][d], i-major
    __shared__ float shP[1020];         // shP[(k*4+h)*15 + p]
    int t = threadIdx.x;                // 256 threads; t = d*4 + i
    int d = t >> 2, i = t & 3;
    float a = 0.f;
#pragma unroll
    for (int k = 0; k < 16; k++) a = fmaf(W2[i * 16 + k], W[k * 64 + d], a);
    shA[i * 64 + d] = a;
    if (i == 0) {
        float cc = b[d];
#pragma unroll
        for (int k = 0; k < 16; k++) cc = fmaf(b2[k], W[k * 64 + d], cc);
        shA[4 * 64 + d] = cc;
    }
    __syncthreads();

    // P entries: stored scalar in shP
    for (int idx = t; idx < 1020; idx += 256) {
        int h   = idx / 255;
        int rem = idx % 255;
        int k   = rem / 15;
        int p   = rem % 15;
        int pi = c_PI[p], pj = c_PJ[p];
        float s = 0.f;
#pragma unroll
        for (int dd = 0; dd < 16; dd++) {
            int dg = h * 16 + dd;
            float wk = (k < 16) ? W[k * 64 + dg] : b[dg];
            s = fmaf(shA[pi * 64 + dg] * shA[pj * 64 + dg], wk, s);
        }
        shP[(k * 4 + h) * 15 + p] = s;
    }
    __syncthreads();

    // pack head pairs: g_P2[k*32 + hp*16 + p] = (P^{2hp}, P^{2hp+1})
    for (int idx = t; idx < 544; idx += 256) {
        int k  = idx / 32;
        int r  = idx % 32;
        int hp = r / 16;
        int p  = r % 16;
        ull v = 0ull;
        if (p < 15)
            v = pk2(shP[(k * 4 + 2 * hp) * 15 + p], shP[(k * 4 + 2 * hp + 1) * 15 + p]);
        g_P2[idx] = v;
    }

    // out_kernel tables: dup-packed Wout and A/c records
    for (int idx = t; idx < 1024; idx += 256)
        g_Wod[idx] = dupf(Wout[idx]);
    for (int idx = t; idx < 384; idx += 256) {
        int dd = idx / 6, r = idx % 6;
        ull v = 0ull;
        if (r < 4)      v = dupf(shA[r * 64 + dd]);
        else if (r == 4) v = dupf(shA[4 * 64 + dd]);
        g_ACd[idx] = v;
    }
}

// ---------------------------------------------------------------------------
// Kernel A: t4[m] = elu(x*W1 + b1); zero the UZ accumulator row.
// ---------------------------------------------------------------------------
__global__ __launch_bounds__(256)
void t4_kernel(const float* __restrict__ ev,
               const float* __restrict__ W1, const float* __restrict__ b1) {
    __shared__ float sW1[4], sb1[4];
    int t = threadIdx.x;
    if (t < 4) { sW1[t] = W1[t]; sb1[t] = b1[t]; }
    __syncthreads();

    int m = blockIdx.x * blockDim.x + t;
    if (m >= M_NODES) return;

    float x = ev[m];
    float4 t4;
    t4.x = elu1(fmaf(x, sW1[0], sb1[0]));
    t4.y = elu1(fmaf(x, sW1[1], sb1[1]));
    t4.z = elu1(fmaf(x, sW1[2], sb1[2]));
    t4.w = elu1(fmaf(x, sW1[3], sb1[3]));
    reinterpret_cast<float4*>(g_t4)[m] = t4;

    float4 z4 = make_float4(0.f, 0.f, 0.f, 0.f);
    float4* uz = reinterpret_cast<float4*>(g_UZ + (size_t)m * 20);
#pragma unroll
    for (int k = 0; k < 5; k++) uz[k] = z4;
}

// ---------------------------------------------------------------------------
// dot2x14p: H1 = m1 . Prow(0..13) + Prow[14], H2 = m2 . Prow(0..13) + Prow[14]
// ONE row load (8 x LDS.128) serves BOTH dot chains.
// ---------------------------------------------------------------------------
__device__ __forceinline__ void dot2x14p(const ull* m1, const ull* m2v,
                                         const ull* Pr, ull& H1, ull& H2) {
    const ulonglong2* r2 = reinterpret_cast<const ulonglong2*>(Pr);
    ulonglong2 q0 = r2[0], q1 = r2[1], q2 = r2[2], q3 = r2[3];
    ulonglong2 q4 = r2[4], q5 = r2[5], q6 = r2[6], q7 = r2[7];

    ull a = mul2(m1[0], q0.x);
    fma2(a, m1[1], q0.y); fma2(a, m1[2], q1.x); fma2(a, m1[3], q1.y); fma2(a, m1[4], q2.x);
    ull b = mul2(m1[5], q2.y);
    fma2(b, m1[6], q3.x); fma2(b, m1[7], q3.y); fma2(b, m1[8], q4.x); fma2(b, m1[9], q4.y);
    ull c = mul2(m1[10], q5.x);
    fma2(c, m1[11], q5.y); fma2(c, m1[12], q6.x); fma2(c, m1[13], q6.y);
    H1 = add2(add2(a, b), add2(c, q7.x));

    ull d = mul2(m2v[0], q0.x);
    fma2(d, m2v[1], q0.y); fma2(d, m2v[2], q1.x); fma2(d, m2v[3], q1.y); fma2(d, m2v[4], q2.x);
    ull e = mul2(m2v[5], q2.y);
    fma2(e, m2v[6], q3.x); fma2(e, m2v[7], q3.y); fma2(e, m2v[8], q4.x); fma2(e, m2v[9], q4.y);
    ull f = mul2(m2v[10], q5.x);
    fma2(f, m2v[11], q5.y); fma2(f, m2v[12], q6.x); fma2(f, m2v[13], q6.y);
    H2 = add2(add2(d, e), add2(f, q7.x));
}

// scalar m_p for one edge, then dup-packed (head-pair lanes need identical m)
__device__ __forceinline__ void make_m_dup(const float4& ts, const float4& tq, ull* m) {
    m[0]  = dupf(ts.x * tq.x);
    m[1]  = dupf(fmaf(ts.x, tq.y, ts.y * tq.x));
    m[2]  = dupf(fmaf(ts.x, tq.z, ts.z * tq.x));
    m[3]  = dupf(fmaf(ts.x, tq.w, ts.w * tq.x));
    m[4]  = dupf(ts.x + tq.x);
    m[5]  = dupf(ts.y * tq.y);
    m[6]  = dupf(fmaf(ts.y, tq.z, ts.z * tq.y));
    m[7]  = dupf(fmaf(ts.y, tq.w, ts.w * tq.y));
    m[8]  = dupf(ts.y + tq.y);
    m[9]  = dupf(ts.z * tq.z);
    m[10] = dupf(fmaf(ts.z, tq.w, ts.w * tq.z));
    m[11] = dupf(ts.z + tq.z);
    m[12] = dupf(ts.w * tq.w);
    m[13] = dupf(ts.w + tq.w);
}

// ---------------------------------------------------------------------------
// Kernel B: TWO edges per thread; f32x2 lanes = (head h, head h+1).
// m dup-packed per edge; every P2-row load (8 LDS.128) feeds BOTH edges.
// (unchanged from R16 — best measured: 90.3 us)
// ---------------------------------------------------------------------------
__global__ __launch_bounds__(128, 4)
void edge_kernel(const void* __restrict__ ei_raw,
                 const float* __restrict__ ef,
                 const float* __restrict__ W2, const float* __restrict__ b2) {
    __shared__ ull    sP2[544];        // [k][hp][p-pair], 4.25 KB
    __shared__ float4 sW2r[16];        // row k: (W2[0,k],W2[1,k],W2[2,k],W2[3,k])
    __shared__ float  sb2[16];

    int t = threadIdx.x;
    for (int i = t; i < 544; i += 128) sP2[i] = g_P2[i];
    if (t < 16) {
        sW2r[t] = make_float4(W2[t], W2[16 + t], W2[32 + t], W2[48 + t]);
        sb2[t] = b2[t];
    }
    __syncthreads();

    int ea = blockIdx.x * blockDim.x + t;
    if (ea >= NE_HALF) return;
    int eb = ea + NE_HALF;

    int srcA, dstA, srcB, dstB;
    if (g_idx_is_64) {
        const long long* ei = (const long long*)ei_raw;
        srcA = (int)__ldg(ei + ea);
        dstA = (int)__ldg(ei + NE_EDGES + ea);
        srcB = (int)__ldg(ei + eb);
        dstB = (int)__ldg(ei + NE_EDGES + eb);
    } else {
        const int* ei = (const int*)ei_raw;
        srcA = __ldg(ei + ea);
        dstA = __ldg(ei + NE_EDGES + ea);
        srcB = __ldg(ei + eb);
        dstB = __ldg(ei + NE_EDGES + eb);
    }

    const float4* t4p = reinterpret_cast<const float4*>(g_t4);
    float4 efA = __ldg(reinterpret_cast<const float4*>(ef) + ea);
    float4 efB = __ldg(reinterpret_cast<const float4*>(ef) + eb);

    // m tensors (dup-packed); ts/tq die after this block
    ull mA[14], mB[14];
    {
        float4 tsA = __ldg(t4p + srcA), tqA = __ldg(t4p + dstA);
        float4 tsB = __ldg(t4p + srcB), tqB = __ldg(t4p + dstB);
        make_m_dup(tsA, tqA, mA);
        make_m_dup(tsB, tqB, mB);
    }

    // sc[edge][hp], lanes = (h0,h1) / (h2,h3); init from bias row k=16
    ull scA[2], scB[2];
#pragma unroll
    for (int hp = 0; hp < 2; hp++)
        dot2x14p(mA, mB, sP2 + 16 * 32 + hp * 16, scA[hp], scB[hp]);

    // main k loop: e16 in-loop; each row load feeds both edges
#pragma unroll
    for (int k = 0; k < 16; k++) {
        float4 w = sW2r[k];
        float bb = sb2[k];
        float va = fmaf(efA.x, w.x, fmaf(efA.y, w.y, fmaf(efA.z, w.z, fmaf(efA.w, w.w, bb))));
        float vb = fmaf(efB.x, w.x, fmaf(efB.y, w.y, fmaf(efB.z, w.z, fmaf(efB.w, w.w, bb))));
        ull ekA = dupf(elu1(va));
        ull ekB = dupf(elu1(vb));
#pragma unroll
        for (int hp = 0; hp < 2; hp++) {
            ull HA, HB;
            dot2x14p(mA, mB, sP2 + k * 32 + hp * 16, HA, HB);
            fma2(scA[hp], ekA, HA);
            fma2(scB[hp], ekB, HB);
        }
    }

    // epilogue: re-gather ts (L1-hot), exp + scatter
    float4 tsA = __ldg(t4p + srcA);
    float4 tsB = __ldg(t4p + srcB);

    float* uzA = g_UZ + (size_t)dstA * 20;
    float* uzB = g_UZ + (size_t)dstB * 20;

    float sA0, sA1, sA2, sA3, sB0, sB1, sB2, sB3;
    upk2(sA0, sA1, scA[0]); upk2(sA2, sA3, scA[1]);
    upk2(sB0, sB1, scB[0]); upk2(sB2, sB3, scB[1]);

    float wA0 = __expf(fminf(fmaxf(sA0 * 0.25f, -5.0f), 5.0f));
    float wA1 = __expf(fminf(fmaxf(sA1 * 0.25f, -5.0f), 5.0f));
    float wA2 = __expf(fminf(fmaxf(sA2 * 0.25f, -5.0f), 5.0f));
    float wA3 = __expf(fminf(fmaxf(sA3 * 0.25f, -5.0f), 5.0f));
    float wB0 = __expf(fminf(fmaxf(sB0 * 0.25f, -5.0f), 5.0f));
    float wB1 = __expf(fminf(fmaxf(sB1 * 0.25f, -5.0f), 5.0f));
    float wB2 = __expf(fminf(fmaxf(sB2 * 0.25f, -5.0f), 5.0f));
    float wB3 = __expf(fminf(fmaxf(sB3 * 0.25f, -5.0f), 5.0f));

    red_add_v4(uzA +  0, make_float4(tsA.x * wA0, tsA.y * wA0, tsA.z * wA0, tsA.w * wA0));
    red_add_v4(uzA +  4, make_float4(tsA.x * wA1, tsA.y * wA1, tsA.z * wA1, tsA.w * wA1));
    red_add_v4(uzA +  8, make_float4(tsA.x * wA2, tsA.y * wA2, tsA.z * wA2, tsA.w * wA2));
    red_add_v4(uzA + 12, make_float4(tsA.x * wA3, tsA.y * wA3, tsA.z * wA3, tsA.w * wA3));
    red_add_v4(uzA + 16, make_float4(wA0, wA1, wA2, wA3));

    red_add_v4(uzB +  0, make_float4(tsB.x * wB0, tsB.y * wB0, tsB.z * wB0, tsB.w * wB0));
    red_add_v4(uzB +  4, make_float4(tsB.x * wB1, tsB.y * wB1, tsB.z * wB1, tsB.w * wB1));
    red_add_v4(uzB +  8, make_float4(tsB.x * wB2, tsB.y * wB2, tsB.z * wB2, tsB.w * wB2));
    red_add_v4(uzB + 12, make_float4(tsB.x * wB3, tsB.y * wB3, tsB.z * wB3, tsB.w * wB3));
    red_add_v4(uzB + 16, make_float4(wB0, wB1, wB2, wB3));
}

// ---------------------------------------------------------------------------
// Kernel C v2: TWO nodes per thread, f32x2 lanes = (nodeA, nodeB).
// wV_d = A[:,d].U_h + c_d*Z_h ; h_d = wV_d/(Z_h+1e-6);
// out = elu(h @ Wout + bout) @ Wout1 + bout1
// ---------------------------------------------------------------------------
__global__ __launch_bounds__(128)
void out_kernel(float* __restrict__ out,
                const float* __restrict__ bout,
                const float* __restrict__ Wout1, const float* __restrict__ bout1) {
    __shared__ ull  sWo[1024];         // [d][k] dup, 8 KB
    __shared__ ull  sAC[384];          // [d]{A0,A1,A2,A3,c,pad} dup, 3 KB
    __shared__ float sbo[16], sW1[16], sb1;

    int t = threadIdx.x;
    for (int i = t; i < 1024; i += 128) sWo[i] = g_Wod[i];
    for (int i = t; i < 384; i += 128) sAC[i] = g_ACd[i];
    if (t < 16) { sbo[t] = bout[t]; sW1[t] = Wout1[t]; }
    if (t == 0) sb1 = bout1[0];
    __syncthreads();

    int mA = blockIdx.x * blockDim.x + t;
    if (mA >= M_HALF) return;
    int mB = mA + M_HALF;

    const float4* uzA = reinterpret_cast<const float4*>(g_UZ + (size_t)mA * 20);
    const float4* uzB = reinterpret_cast<const float4*>(g_UZ + (size_t)mB * 20);
    float4 UA[4] = {uzA[0], uzA[1], uzA[2], uzA[3]};
    float4 UB[4] = {uzB[0], uzB[1], uzB[2], uzB[3]};
    float4 ZA = uzA[4], ZB = uzB[4];

    // pack U/Z per head, lanes = (A,B)
    ull U2[4][4], Z2[4], rz2[4];
#pragma unroll
    for (int h = 0; h < 4; h++) {
        const float* ua = reinterpret_cast<const float*>(&UA[h]);
        const float* ub = reinterpret_cast<const float*>(&UB[h]);
#pragma unroll
        for (int i = 0; i < 4; i++) U2[h][i] = pk2(ua[i], ub[i]);
    }
    {
        const float* za = reinterpret_cast<const float*>(&ZA);
        const float* zb = reinterpret_cast<const float*>(&ZB);
#pragma unroll
        for (int h = 0; h < 4; h++) {
            Z2[h]  = pk2(za[h], zb[h]);
            rz2[h] = pk2(1.0f / (za[h] + 1e-6f), 1.0f / (zb[h] + 1e-6f));
        }
    }

    ull acc2[16];
#pragma unroll
    for (int k = 0; k < 16; k++) acc2[k] = dupf(sbo[k]);

#pragma unroll
    for (int h = 0; h < 4; h++) {
        ull zz = Z2[h], rr = rz2[h];
#pragma unroll
        for (int dd = 0; dd < 16; dd++) {
            int d = h * 16 + dd;
            const ulonglong2* ac = reinterpret_cast<const ulonglong2*>(sAC + d * 6);
            ulonglong2 x0 = ac[0];    // A0, A1
            ulonglong2 x1 = ac[1];    // A2, A3
            ulonglong2 x2 = ac[2];    // c, pad
            ull wv = mul2(x2.x, zz);
            fma2(wv, U2[h][0], x0.x); fma2(wv, U2[h][1], x0.y);
            fma2(wv, U2[h][2], x1.x); fma2(wv, U2[h][3], x1.y);
            ull hv = mul2(wv, rr);

            const ulonglong2* wo = reinterpret_cast<const ulonglong2*>(sWo + d * 16);
#pragma unroll
            for (int q = 0; q < 8; q++) {
                ulonglong2 ww = wo[q];
                fma2(acc2[2 * q],     hv, ww.x);
                fma2(acc2[2 * q + 1], hv, ww.y);
            }
        }
    }

    float valA = sb1, valB = sb1;
#pragma unroll
    for (int k = 0; k < 16; k++) {
        float aA, aB;
        upk2(aA, aB, acc2[k]);
        valA = fmaf(elu1(aA), sW1[k], valA);
        valB = fmaf(elu1(aB), sW1[k], valB);
    }
    out[mA] = valA;
    out[mB] = valB;
}

// ---------------------------------------------------------------------------
extern "C" void kernel_launch(void* const* d_in, const int* in_sizes, int n_in,
                              void* d_out, int out_size) {
    // order: node_attr, edge_index, edge_feature, edge_vector,
    //        W1, b1, W2, b2, W, b, Wout, bout, Wout1, bout1
    const void*  ei   = d_in[1];
    const float* ef   = (const float*)d_in[2];
    const float* ev   = (const float*)d_in[3];
    const float* W1   = (const float*)d_in[4];
    const float* b1   = (const float*)d_in[5];
    const float* W2   = (const float*)d_in[6];
    const float* b2   = (const float*)d_in[7];
    const float* W    = (const float*)d_in[8];
    const float* b    = (const float*)d_in[9];
    const float* Wout = (const float*)d_in[10];
    const float* bout = (const float*)d_in[11];
    const float* Wout1= (const float*)d_in[12];
    const float* bout1= (const float*)d_in[13];
    float* out = (float*)d_out;

    probe_idx_kernel<<<1, 1>>>((const int*)ei);
    setup_kernel<<<1, 256>>>(W2, b2, W, b, Wout);
    t4_kernel<<<(M_NODES + 255) / 256, 256>>>(ev, W1, b1);
    edge_kernel<<<(NE_HALF + 127) / 128, 128>>>(ei, ef, W2, b2);
    out_kernel<<<(M_HALF + 127) / 128, 128>>>(out, bout, Wout1, bout1);
}